// round 1
// baseline (speedup 1.0000x reference)
#include <cuda_runtime.h>

// Problem constants
#define B_  2
#define T_  4096
#define H_  8
#define D_  64
#define C_  64                 // chunk length (== D, minimizes work)
#define NC_ (T_/C_)            // 64 chunks
#define BH_ (B_*H_)            // 16
#define ROWSTRIDE (H_*D_)      // 512 floats between consecutive t

// Scratch: per-(bh,chunk) DxD matrix. Pass1 writes chunk sums, pass2 converts
// in-place to the EXCLUSIVE prefix (state M before each chunk). 16 MB.
__device__ float g_S[(size_t)BH_ * NC_ * D_ * D_];

// ---------------------------------------------------------------------------
// Pass 1: S[bh][c][d][e] = sum_{s in chunk} V[s][d] * K[s][e]
// One CTA per (bh, chunk). 256 threads, 4x4 register tiles.
// ---------------------------------------------------------------------------
__global__ void __launch_bounds__(256) chunk_sum_kernel(const float* __restrict__ k,
                                                        const float* __restrict__ v) {
    int blk = blockIdx.x;
    int bh  = blk >> 6;          // / NC_
    int c   = blk & (NC_ - 1);
    int b   = bh >> 3, h = bh & 7;

    __shared__ float Ks[C_][D_];   // [s][e]
    __shared__ float Vs[C_][D_];   // [s][d]

    const float* kbase = k + (((size_t)b * T_ + (size_t)c * C_) * H_ + h) * D_;
    const float* vbase = v + (((size_t)b * T_ + (size_t)c * C_) * H_ + h) * D_;

    int tid = threadIdx.x;
    #pragma unroll
    for (int f = tid; f < C_ * D_ / 4; f += 256) {
        int s = f >> 4;              // row in chunk
        int e4 = f & 15;             // float4 column
        ((float4*)Ks)[f] = *(const float4*)(kbase + (size_t)s * ROWSTRIDE + e4 * 4);
        ((float4*)Vs)[f] = *(const float4*)(vbase + (size_t)s * ROWSTRIDE + e4 * 4);
    }
    __syncthreads();

    int ty = tid >> 4, tx = tid & 15;
    int d0 = ty * 4, e0 = tx * 4;
    float acc[4][4] = {};
    #pragma unroll 8
    for (int s = 0; s < C_; s++) {
        float4 vv = *(const float4*)&Vs[s][d0];
        float4 kk = *(const float4*)&Ks[s][e0];
        float va[4] = {vv.x, vv.y, vv.z, vv.w};
        float ka[4] = {kk.x, kk.y, kk.z, kk.w};
        #pragma unroll
        for (int i = 0; i < 4; i++)
            #pragma unroll
            for (int j = 0; j < 4; j++)
                acc[i][j] += va[i] * ka[j];
    }

    float* Sout = g_S + (size_t)blk * D_ * D_;
    #pragma unroll
    for (int i = 0; i < 4; i++)
        *(float4*)&Sout[(d0 + i) * D_ + e0] =
            make_float4(acc[i][0], acc[i][1], acc[i][2], acc[i][3]);
}

// ---------------------------------------------------------------------------
// Pass 2: in-place EXCLUSIVE prefix over the chunk axis for every (bh, d, e).
// One thread per matrix entry; load all 64 chunk values up-front (MLP=64),
// scan in registers, store back. Two DRAM round-trips instead of 64.
// ---------------------------------------------------------------------------
__global__ void __launch_bounds__(256) prefix_kernel() {
    int gidx = blockIdx.x * 256 + threadIdx.x;   // [0, BH_*D_*D_)
    int bh  = gidx >> 12;                        // / 4096
    int idx = gidx & 4095;
    float* base = g_S + (size_t)bh * NC_ * D_ * D_ + idx;

    float vals[NC_];
    #pragma unroll
    for (int c = 0; c < NC_; c++) vals[c] = base[(size_t)c * D_ * D_];
    float run = 0.f;
    #pragma unroll
    for (int c = 0; c < NC_; c++) { float t = vals[c]; vals[c] = run; run += t; }
    #pragma unroll
    for (int c = 0; c < NC_; c++) base[(size_t)c * D_ * D_] = vals[c];
}

// ---------------------------------------------------------------------------
// Pass 3: Y = tril(Q K^T) V + Q M_prev^T  per (bh, chunk) tile.
// Shared operands stored [reduction_dim][output_dim] (+4 pad) so every inner
// loop is two float4 LDS + 16 FFMA per thread.
// ---------------------------------------------------------------------------
#define PAD_ (C_ + 4)   // 68
#define SMEM3_BYTES ((4 * D_ * PAD_ + C_ * D_) * (int)sizeof(float))  // 86016

__global__ void __launch_bounds__(256) output_kernel(const float* __restrict__ q,
                                                     const float* __restrict__ k,
                                                     const float* __restrict__ v,
                                                     float* __restrict__ y) {
    extern __shared__ float sm[];
    float (*Qt)[PAD_] = (float(*)[PAD_])(sm);                    // [e][t]
    float (*Kt)[PAD_] = (float(*)[PAD_])(sm + 1 * D_ * PAD_);    // [e][s]
    float (*Mt)[PAD_] = (float(*)[PAD_])(sm + 2 * D_ * PAD_);    // [e][d]  (M[d][e] transposed)
    float (*At)[PAD_] = (float(*)[PAD_])(sm + 3 * D_ * PAD_);    // [s][t]
    float (*Vs)[D_]   = (float(*)[D_])  (sm + 4 * D_ * PAD_);    // [s][d]

    int blk = blockIdx.x;
    int bh  = blk >> 6;
    int c   = blk & (NC_ - 1);
    int b   = bh >> 3, h = bh & 7;

    const float* qbase = q + (((size_t)b * T_ + (size_t)c * C_) * H_ + h) * D_;
    const float* kbase = k + (((size_t)b * T_ + (size_t)c * C_) * H_ + h) * D_;
    const float* vbase = v + (((size_t)b * T_ + (size_t)c * C_) * H_ + h) * D_;
    const float* Mbase = g_S + (size_t)blk * D_ * D_;

    int tid = threadIdx.x;
    #pragma unroll
    for (int f = tid; f < C_ * D_ / 4; f += 256) {
        int r = f >> 4;      // row (t for q/k/v, d for M)
        int c4 = f & 15;     // float4 column index
        int cc = c4 * 4;
        float4 qv = *(const float4*)(qbase + (size_t)r * ROWSTRIDE + cc);
        Qt[cc + 0][r] = qv.x; Qt[cc + 1][r] = qv.y; Qt[cc + 2][r] = qv.z; Qt[cc + 3][r] = qv.w;
        float4 kv = *(const float4*)(kbase + (size_t)r * ROWSTRIDE + cc);
        Kt[cc + 0][r] = kv.x; Kt[cc + 1][r] = kv.y; Kt[cc + 2][r] = kv.z; Kt[cc + 3][r] = kv.w;
        float4 vv = *(const float4*)(vbase + (size_t)r * ROWSTRIDE + cc);
        ((float4*)Vs)[f] = vv;
        float4 mv = *(const float4*)(Mbase + f * 4);
        Mt[cc + 0][r] = mv.x; Mt[cc + 1][r] = mv.y; Mt[cc + 2][r] = mv.z; Mt[cc + 3][r] = mv.w;
    }
    __syncthreads();

    int ty = tid >> 4, tx = tid & 15;
    int t0 = ty * 4, s0 = tx * 4;

    // Phase A: A[t][s] = sum_e Q[t][e]*K[s][e], causal mask s <= t (inclusive)
    {
        float acc[4][4] = {};
        #pragma unroll 8
        for (int e = 0; e < D_; e++) {
            float4 qq = *(const float4*)&Qt[e][t0];
            float4 kk = *(const float4*)&Kt[e][s0];
            float qa[4] = {qq.x, qq.y, qq.z, qq.w};
            float ka[4] = {kk.x, kk.y, kk.z, kk.w};
            #pragma unroll
            for (int i = 0; i < 4; i++)
                #pragma unroll
                for (int j = 0; j < 4; j++)
                    acc[i][j] += qa[i] * ka[j];
        }
        #pragma unroll
        for (int j = 0; j < 4; j++) {
            int s = s0 + j;
            float4 col;
            col.x = (s <= t0 + 0) ? acc[0][j] : 0.f;
            col.y = (s <= t0 + 1) ? acc[1][j] : 0.f;
            col.z = (s <= t0 + 2) ? acc[2][j] : 0.f;
            col.w = (s <= t0 + 3) ? acc[3][j] : 0.f;
            *(float4*)&At[s][t0] = col;   // store transposed: [s][t]
        }
    }
    __syncthreads();

    // Phase B: Y[t][d] = sum_s A[t][s] V[s][d]  +  sum_e Q[t][e] M[d][e]
    int d0 = tx * 4;
    float out[4][4] = {};
    #pragma unroll 8
    for (int s = 0; s < C_; s++) {
        float4 aa = *(const float4*)&At[s][t0];
        float4 vv = *(const float4*)&Vs[s][d0];
        float av[4] = {aa.x, aa.y, aa.z, aa.w};
        float vw[4] = {vv.x, vv.y, vv.z, vv.w};
        #pragma unroll
        for (int i = 0; i < 4; i++)
            #pragma unroll
            for (int j = 0; j < 4; j++)
                out[i][j] += av[i] * vw[j];
    }
    #pragma unroll 8
    for (int e = 0; e < D_; e++) {
        float4 qq = *(const float4*)&Qt[e][t0];
        float4 mm = *(const float4*)&Mt[e][d0];
        float qa[4] = {qq.x, qq.y, qq.z, qq.w};
        float ma[4] = {mm.x, mm.y, mm.z, mm.w};
        #pragma unroll
        for (int i = 0; i < 4; i++)
            #pragma unroll
            for (int j = 0; j < 4; j++)
                out[i][j] += qa[i] * ma[j];
    }

    float* ybase = y + (((size_t)b * T_ + (size_t)c * C_) * H_ + h) * D_;
    #pragma unroll
    for (int i = 0; i < 4; i++)
        *(float4*)(ybase + (size_t)(t0 + i) * ROWSTRIDE + d0) =
            make_float4(out[i][0], out[i][1], out[i][2], out[i][3]);
}

// ---------------------------------------------------------------------------
extern "C" void kernel_launch(void* const* d_in, const int* in_sizes, int n_in,
                              void* d_out, int out_size) {
    (void)in_sizes; (void)n_in; (void)out_size;
    const float* q = (const float*)d_in[0];
    const float* k = (const float*)d_in[1];
    const float* v = (const float*)d_in[2];
    float* y = (float*)d_out;

    // Opt-in to >48KB dynamic smem for pass 3 (idempotent, capture-safe).
    cudaFuncSetAttribute(output_kernel, cudaFuncAttributeMaxDynamicSharedMemorySize,
                         SMEM3_BYTES);

    chunk_sum_kernel<<<BH_ * NC_, 256>>>(k, v);
    prefix_kernel<<<(BH_ * D_ * D_) / 256, 256>>>();
    output_kernel<<<BH_ * NC_, 256, SMEM3_BYTES>>>(q, k, v, y);
}